// round 13
// baseline (speedup 1.0000x reference)
#include <cuda_runtime.h>

#define NN 2048
#define NTHR 512       // sort width: 16 warps
#define LOOPT 256      // Sinkhorn threads (warps 0..7)
#define LWARPS (LOOPT / 32)
#define EPB 8          // elements per thread (LOOPT*EPB == NN)
#define ITERS 50
#define TOLC 1e-6f

__device__ __forceinline__ float warp_sum(float v) {
    #pragma unroll
    for (int o = 16; o; o >>= 1) v += __shfl_xor_sync(0xffffffffu, v, o);
    return v;
}

// dual scan: forward inclusive on .x, backward inclusive on .y
__device__ __forceinline__ float2 scan_fb(float2 v, int lane) {
    #pragma unroll
    for (int o = 1; o < 32; o <<= 1) {
        float ax = __shfl_up_sync(0xffffffffu, v.x, o);
        float ay = __shfl_down_sync(0xffffffffu, v.y, o);
        if (lane >= o)      v.x += ax;
        if (lane < 32 - o)  v.y += ay;
    }
    return v;
}

// out = W~ x, W~[k][m] = exp(-|s_k - s_m|), s sorted descending.
// Thread owns k = tid*EPB .. +7 contiguous; x in registers; ONE bar.
// (W~x)_k = F_k * prefix_incl_k(x/F) + Fi_k * suffix_excl_k(x*F).
__device__ __forceinline__ void applyW8(
    const float* __restrict__ x, const float* __restrict__ F,
    const float* __restrict__ Fi, float* __restrict__ out,
    float* sA, float* sB, int lane, int warp)
{
    float z[EPB], w[EPB], pz[EPB], sw[EPB + 1];
    #pragma unroll
    for (int e = 0; e < EPB; e++) { z[e] = x[e] * Fi[e]; w[e] = x[e] * F[e]; }
    pz[0] = z[0];
    #pragma unroll
    for (int e = 1; e < EPB; e++) pz[e] = pz[e - 1] + z[e];       // local prefix
    sw[EPB] = 0.0f;
    #pragma unroll
    for (int e = EPB - 1; e >= 0; e--) sw[e] = sw[e + 1] + w[e];  // local suffix

    float2 wp = scan_fb(make_float2(pz[EPB - 1], sw[0]), lane);
    if (lane == 31) sA[warp] = wp.x;
    if (lane == 0)  sB[warp] = wp.y;
    __syncthreads();
    float bz = 0.f, bw = 0.f;
    #pragma unroll
    for (int q = 0; q < LWARPS; q++) {
        float a = sA[q], b = sB[q];
        if (q < warp) bz += a;
        if (q > warp) bw += b;
    }
    float exz = bz + (wp.x - pz[EPB - 1]);
    float exw = bw + (wp.y - sw[0]);
    #pragma unroll
    for (int e = 0; e < EPB; e++)
        out[e] = fmaf(F[e], exz + pz[e], Fi[e] * (exw + sw[e + 1]));
}

__global__ void __launch_bounds__(NTHR, 1)
softndcg_kernel(const float* __restrict__ y_pred,
                const float* __restrict__ y_true,
                float* __restrict__ out)
{
    __shared__ float skey[NN];   // scores (sorted descending after network)
    __shared__ float sval[NN];   // labels carried with scores (score-rank basis)
    __shared__ float slab[NN];   // labels sorted descending (for idcg)
    __shared__ float sA0[LWARPS], sB0[LWARPS];
    __shared__ float sA1[LWARPS], sB1[LWARPS];
    __shared__ float sred[LWARPS];
    __shared__ float s_pi[16];   // idcg warp partials
    __shared__ int   sbad[2];    // convergence flags, parity-buffered

    const int tid  = threadIdx.x;
    const int lane = tid & 31;
    const int warp = tid >> 5;

    // ---- load + gain transform ---------------------------------------------
    #pragma unroll
    for (int i = tid; i < NN; i += NTHR) {
        float lab = exp2f(__ldg(&y_true[i])) - 1.0f;
        skey[i] = __ldg(&y_pred[i]);
        sval[i] = lab;
        slab[i] = lab;
    }

    // ---- bitonic sort, descending: (skey,sval) by skey; slab by value ------
    for (unsigned k = 2; k <= NN; k <<= 1) {
        for (unsigned j = k >> 1; j > 0; j >>= 1) {
            __syncthreads();
            #pragma unroll
            for (int i = tid; i < NN; i += NTHR) {
                unsigned l = (unsigned)i ^ j;
                if (l > (unsigned)i) {
                    bool up = ((i & k) == 0);   // descending network
                    float ai = skey[i], al = skey[l];
                    if (up ? (ai < al) : (ai > al)) {
                        skey[i] = al; skey[l] = ai;
                        float t = sval[i]; sval[i] = sval[l]; sval[l] = t;
                    }
                    float bi = slab[i], bl = slab[l];
                    if (up ? (bi < bl) : (bi > bl)) {
                        slab[i] = bl; slab[l] = bi;
                    }
                }
            }
        }
    }
    __syncthreads();

    // ---- idcg partials (all 16 warps, 4 elements/thread) -------------------
    {
        float p = 0.f;
        #pragma unroll
        for (int e = 0; e < 4; e++) {
            int r = tid * 4 + e;
            p += slab[r] / log2f((float)r + 2.0f);
        }
        p = warp_sum(p);
        if (lane == 0) s_pi[warp] = p;   // consumed after later bars
    }
    if (tid >= LOOPT) return;            // warps 8..15 done

    // ---- prologue: per-thread constants (8 contiguous elements) ------------
    const int base_k = tid * EPB;
    float F[EPB], Fi[EPB], L[EPB];
    #pragma unroll
    for (int e = 0; e < EPB; e++) {
        float s = skey[base_k + e];
        F[e]  = expf(s);
        Fi[e] = 1.0f / F[e];
        L[e]  = sval[base_k + e];
    }
    if (tid == 0) { sbad[0] = 0; sbad[1] = 0; }  // fenced by u0-applyW's bar

    // ---- u0 = 1 / rowsum(W~), v0 = 1  (buffer 0) ---------------------------
    float u[EPB], v[EPB], x[EPB], o[EPB];
    #pragma unroll
    for (int e = 0; e < EPB; e++) { x[e] = 1.0f; v[e] = 1.0f; }
    applyW8(x, F, Fi, o, sA0, sB0, lane, warp);
    #pragma unroll
    for (int e = 0; e < EPB; e++) u[e] = __fdividef(1.0f, o[e]);

    // ---- Sinkhorn: up to 50 iterations, early exit on convergence ----------
    #pragma unroll 1
    for (int t = 0; t < ITERS; t++) {
        const int par = t & 1;
        // col step: colsum check piggybacks; v <- 1/(W~ u)
        applyW8(u, F, Fi, o, sA1, sB1, lane, warp);
        {
            float dv = 0.f;
            #pragma unroll
            for (int e = 0; e < EPB; e++)
                dv = fmaxf(dv, fabsf(fmaf(v[e], o[e], -1.0f)));
            if (dv >= TOLC) sbad[par] = 1;       // benign same-value race
            if (tid == 0) sbad[par ^ 1] = 0;     // recycle other slot
            #pragma unroll
            for (int e = 0; e < EPB; e++) v[e] = __fdividef(1.0f, o[e]);
        }
        // row step: u <- 1/(W~ v); its bar publishes sbad[par]
        applyW8(v, F, Fi, o, sA0, sB0, lane, warp);
        #pragma unroll
        for (int e = 0; e < EPB; e++) u[e] = __fdividef(1.0f, o[e]);
        if (!sbad[par]) break;                   // uniform: post-bar broadcast
    }

    // ---- Final: dcg = sum_k u_k * (W~ (v .* labs))_k / disc_k --------------
    {
        #pragma unroll
        for (int e = 0; e < EPB; e++) x[e] = v[e] * L[e];
        applyW8(x, F, Fi, o, sA1, sB1, lane, warp);
        float d = 0.f;
        #pragma unroll
        for (int e = 0; e < EPB; e++)
            d += u[e] * o[e] / log2f((float)(base_k + e) + 2.0f);
        d = warp_sum(d);
        if (lane == 0) sred[warp] = d;
        __syncthreads();
        if (tid == 0) {
            float q = 0.f, idcg = 0.f;
            #pragma unroll
            for (int i = 0; i < LWARPS; i++) q += sred[i];
            #pragma unroll
            for (int i = 0; i < 16; i++) idcg += s_pi[i];
            out[0] = 1.0f - q / idcg;
        }
    }
}

extern "C" void kernel_launch(void* const* d_in, const int* in_sizes, int n_in,
                              void* d_out, int out_size) {
    const float* y_pred = (const float*)d_in[0];
    const float* y_true = (const float*)d_in[1];
    float* out = (float*)d_out;
    (void)in_sizes; (void)n_in; (void)out_size;
    softndcg_kernel<<<1, NTHR>>>(y_pred, y_true, out);
}

// round 16
// speedup vs baseline: 2.6153x; 2.6153x over previous
#include <cuda_runtime.h>

#define NN 2048
#define NTHR 512       // 16 warps: one rank-row per warp
#define LOOPT 256      // Sinkhorn threads (CTA0 warps 0..7)
#define LWARPS (LOOPT / 32)
#define EPB 8          // elements per thread (LOOPT*EPB == NN)
#define NBLK 128       // 128 CTAs x 16 warps = 2048 rows exactly
#define ITERS 50
#define TOLC 1e-6f

// ---------------- device scratch (static, per harness rules) ---------------
__device__ float g_s[NN];      // scores sorted descending
__device__ float g_labs[NN];   // labels permuted by score-rank
__device__ float g_part0[NN];  // idcg partials
__device__ unsigned g_arrive = 0;   // monotonic CTA-arrival counter
__device__ unsigned g_base2  = 0;   // CTA0-private replay base

// ---------------- scoped ops (no CCTL.IVALL — preserve caches) -------------
__device__ __forceinline__ unsigned ld_acq(const unsigned* p) {
    unsigned v;
    asm volatile("ld.acquire.gpu.u32 %0, [%1];" : "=r"(v) : "l"(p) : "memory");
    return v;
}
__device__ __forceinline__ void st_rlx(unsigned* p, unsigned v) {
    asm volatile("st.relaxed.gpu.u32 [%0], %1;" :: "l"(p), "r"(v) : "memory");
}
__device__ __forceinline__ unsigned atom_add_rel(unsigned* p, unsigned v) {
    unsigned o;
    asm volatile("atom.add.release.gpu.u32 %0, [%1], %2;"
                 : "=r"(o) : "l"(p), "r"(v) : "memory");
    return o;
}
__device__ __forceinline__ float frcp(float x) {
    float r;
    asm("rcp.approx.ftz.f32 %0, %1;" : "=f"(r) : "f"(x));
    return r;
}

__device__ __forceinline__ float warp_sum(float v) {
    #pragma unroll
    for (int o = 16; o; o >>= 1) v += __shfl_xor_sync(0xffffffffu, v, o);
    return v;
}

// dual scan: forward inclusive on .x, backward inclusive on .y
__device__ __forceinline__ float2 scan_fb(float2 v, int lane) {
    #pragma unroll
    for (int o = 1; o < 32; o <<= 1) {
        float ax = __shfl_up_sync(0xffffffffu, v.x, o);
        float ay = __shfl_down_sync(0xffffffffu, v.y, o);
        if (lane >= o)      v.x += ax;
        if (lane < 32 - o)  v.y += ay;
    }
    return v;
}

// out = W~ x, W~[k][m] = exp(-|s_k - s_m|), s sorted descending.
// Thread owns k = tid*EPB .. +7 contiguous; x in registers; ONE bar.
// (W~x)_k = F_k * prefix_incl_k(x/F) + Fi_k * suffix_excl_k(x*F).
__device__ __forceinline__ void applyW8(
    const float* __restrict__ x, const float* __restrict__ F,
    const float* __restrict__ Fi, float* __restrict__ out,
    float* sA, float* sB, int lane, int warp)
{
    float z[EPB], w[EPB], pz[EPB], sw[EPB + 1];
    #pragma unroll
    for (int e = 0; e < EPB; e++) { z[e] = x[e] * Fi[e]; w[e] = x[e] * F[e]; }
    pz[0] = z[0];
    #pragma unroll
    for (int e = 1; e < EPB; e++) pz[e] = pz[e - 1] + z[e];       // local prefix
    sw[EPB] = 0.0f;
    #pragma unroll
    for (int e = EPB - 1; e >= 0; e--) sw[e] = sw[e + 1] + w[e];  // local suffix

    float2 wp = scan_fb(make_float2(pz[EPB - 1], sw[0]), lane);
    if (lane == 31) sA[warp] = wp.x;
    if (lane == 0)  sB[warp] = wp.y;
    __syncthreads();
    float bz = 0.f, bw = 0.f;
    #pragma unroll
    for (int q = 0; q < LWARPS; q++) {
        float a = sA[q], b = sB[q];
        if (q < warp) bz += a;
        if (q > warp) bw += b;
    }
    float exz = bz + (wp.x - pz[EPB - 1]);
    float exw = bw + (wp.y - sw[0]);
    #pragma unroll
    for (int e = 0; e < EPB; e++)
        out[e] = fmaf(F[e], exz + pz[e], Fi[e] * (exw + sw[e + 1]));
}

__global__ void __launch_bounds__(NTHR, 1)
softndcg_kernel(const float* __restrict__ y_pred,
                const float* __restrict__ y_true,
                float* __restrict__ out)
{
    __shared__ float sA0[LWARPS], sB0[LWARPS];  // scan buffer 0 (row steps)
    __shared__ float sA1[LWARPS], sB1[LWARPS];  // scan buffer 1 (col steps)
    __shared__ float sred[LWARPS];
    __shared__ float s_p8[8];                   // idcg partials, warps 8..15
    __shared__ int   sbad[2];                   // convergence flags, parity

    const int tid  = threadIdx.x;
    const int lane = tid & 31;
    const int warp = tid >> 5;
    const int bid  = blockIdx.x;

    // ---- Setup: one rank-row per warp; float4 + full unroll (MLP ~32) ------
    {
        const int r = bid * 16 + warp;
        const float ai = __ldg(&y_pred[r]);
        const float ti = __ldg(&y_true[r]);
        const float4* yp4 = reinterpret_cast<const float4*>(y_pred);
        const float4* yt4 = reinterpret_cast<const float4*>(y_true);
        int ca = 0, cl = 0;
        #pragma unroll
        for (int k = 0; k < 16; k++) {
            const int q = lane + 32 * k;       // float4 index, 0..511
            float4 a4 = __ldg(yp4 + q);
            float4 t4 = __ldg(yt4 + q);
            const int jb = 4 * q;
            ca += (a4.x > ai) || (a4.x == ai && jb + 0 < r);
            ca += (a4.y > ai) || (a4.y == ai && jb + 1 < r);
            ca += (a4.z > ai) || (a4.z == ai && jb + 2 < r);
            ca += (a4.w > ai) || (a4.w == ai && jb + 3 < r);
            cl += (t4.x > ti) || (t4.x == ti && jb + 0 < r);
            cl += (t4.y > ti) || (t4.y == ti && jb + 1 < r);
            cl += (t4.z > ti) || (t4.z == ti && jb + 2 < r);
            cl += (t4.w > ti) || (t4.w == ti && jb + 3 < r);
        }
        #pragma unroll
        for (int o = 16; o; o >>= 1) {
            ca += __shfl_xor_sync(0xffffffffu, ca, o);
            cl += __shfl_xor_sync(0xffffffffu, cl, o);
        }
        if (lane == 0) {
            float lab = exp2f(ti) - 1.0f;
            g_s[ca]    = ai;                           // descending-sorted scores
            g_labs[ca] = lab;                          // score-rank basis labels
            g_part0[r] = lab / log2f((float)cl + 2.0f);  // idcg term at rank cl
        }
    }

    // ---- Arrival-only sync: workers leave immediately ----------------------
    unsigned base = 0;
    if (bid == 0) base = __ldcg(&g_base2);  // replay-safe target base
    __syncthreads();                        // CTA's writes ordered before arrive
    if (tid == 0) atom_add_rel(&g_arrive, 1u);
    if (bid != 0) return;

    // CTA0: ONLY tid 0 polls (no 16-warp strong-load storm on the counter)
    if (tid == 0) {
        const unsigned target = base + NBLK;
        while ((int)(ld_acq(&g_arrive) - target) < 0) { }
    }
    __syncthreads();   // broadcasts arrival; L2-visible data read via __ldcg

    // ---- warps 8..15: idcg partials in parallel with prologue, then exit ---
    if (tid >= LOOPT) {
        const int widx = tid - LOOPT;          // 0..255
        const float4* p4 = reinterpret_cast<const float4*>(g_part0);
        float4 pa = __ldcg(p4 + 2 * widx);
        float4 pb = __ldcg(p4 + 2 * widx + 1);
        float p = ((pa.x + pa.y) + (pa.z + pa.w)) + ((pb.x + pb.y) + (pb.z + pb.w));
        p = warp_sum(p);
        if (lane == 0) s_p8[warp - LWARPS] = p;  // ordered by first loop bar
        return;
    }

    // ---- warps 0..7: prologue (8 contiguous elements per thread) -----------
    const int base_k = tid * EPB;
    float F[EPB], Fi[EPB], L[EPB];
    {
        float4 sa = __ldcg(reinterpret_cast<const float4*>(&g_s[base_k]));
        float4 sb = __ldcg(reinterpret_cast<const float4*>(&g_s[base_k + 4]));
        float4 la = __ldcg(reinterpret_cast<const float4*>(&g_labs[base_k]));
        float4 lb = __ldcg(reinterpret_cast<const float4*>(&g_labs[base_k + 4]));
        float sv[EPB] = {sa.x, sa.y, sa.z, sa.w, sb.x, sb.y, sb.z, sb.w};
        #pragma unroll
        for (int e = 0; e < EPB; e++) { F[e] = expf(sv[e]); Fi[e] = 1.0f / F[e]; }
        L[0]=la.x; L[1]=la.y; L[2]=la.z; L[3]=la.w;
        L[4]=lb.x; L[5]=lb.y; L[6]=lb.z; L[7]=lb.w;
    }
    if (tid == 0) { sbad[0] = 0; sbad[1] = 0; }  // fenced by u0-applyW's bar

    // ---- u0 = 1 / rowsum(W~), v0 = 1  (buffer 0) ---------------------------
    float u[EPB], v[EPB], x[EPB], o[EPB];
    #pragma unroll
    for (int e = 0; e < EPB; e++) { x[e] = 1.0f; v[e] = 1.0f; }
    applyW8(x, F, Fi, o, sA0, sB0, lane, warp);
    #pragma unroll
    for (int e = 0; e < EPB; e++) u[e] = frcp(o[e]);

    // ---- Sinkhorn: up to 50 iterations, early exit on convergence ----------
    #pragma unroll 1
    for (int t = 0; t < ITERS; t++) {
        const int par = t & 1;
        // col step: colsum check piggybacks; v <- 1/(W~ u)
        applyW8(u, F, Fi, o, sA1, sB1, lane, warp);
        {
            float dv = 0.f;
            #pragma unroll
            for (int e = 0; e < EPB; e++)
                dv = fmaxf(dv, fabsf(fmaf(v[e], o[e], -1.0f)));
            if (dv >= TOLC) sbad[par] = 1;       // benign same-value race
            if (tid == 0) sbad[par ^ 1] = 0;     // recycle other slot
            #pragma unroll
            for (int e = 0; e < EPB; e++) v[e] = frcp(o[e]);
        }
        // row step: u <- 1/(W~ v); its bar publishes sbad[par]
        applyW8(v, F, Fi, o, sA0, sB0, lane, warp);
        #pragma unroll
        for (int e = 0; e < EPB; e++) u[e] = frcp(o[e]);
        if (!sbad[par]) break;                   // uniform: post-bar broadcast
    }

    // ---- Final: dcg = sum_k u_k * (W~ (v .* labs))_k / disc_k --------------
    {
        #pragma unroll
        for (int e = 0; e < EPB; e++) x[e] = v[e] * L[e];
        applyW8(x, F, Fi, o, sA1, sB1, lane, warp);
        float d = 0.f;
        #pragma unroll
        for (int e = 0; e < EPB; e++)
            d += u[e] * o[e] / log2f((float)(base_k + e) + 2.0f);
        d = warp_sum(d);
        if (lane == 0) sred[warp] = d;
        __syncthreads();
        if (tid == 0) {
            float q = 0.f, idcg = 0.f;
            #pragma unroll
            for (int i = 0; i < LWARPS; i++) { q += sred[i]; idcg += s_p8[i]; }
            out[0] = 1.0f - q / idcg;
            st_rlx(&g_base2, base + NBLK);       // advance replay base
        }
    }
}

extern "C" void kernel_launch(void* const* d_in, const int* in_sizes, int n_in,
                              void* d_out, int out_size) {
    const float* y_pred = (const float*)d_in[0];
    const float* y_true = (const float*)d_in[1];
    float* out = (float*)d_out;
    (void)in_sizes; (void)n_in; (void)out_size;
    softndcg_kernel<<<NBLK, NTHR>>>(y_pred, y_true, out);
}